// round 7
// baseline (speedup 1.0000x reference)
#include <cuda_runtime.h>
#include <cuda_bf16.h>

// Device-global scratch (no allocations allowed).
__device__ float g_M1[100 * 100];   // level-1 partials (100 chunk matrices)
__device__ float g_c1[100 * 10];
__device__ float g_M2[10 * 100];    // level-2 partials
__device__ float g_c2[10 * 10];
__device__ float g_M3[100];         // final composed matrix [out][in]
__device__ float g_c3[10];          // final composed bias
__device__ unsigned g_ctr1;         // level-1 arrivals (0..100)
__device__ unsigned g_ctr2;         // level-2 arrivals (0..10)
__device__ unsigned g_flag;         // fold complete
__device__ unsigned g_done;         // CTA-done counter (reset logic)

#define TPB 256
#define NSTAGE 4
#define STAGE_PAIRS 240                      // 8 warps x 30 pairs
#define STAGE_FLOATS (STAGE_PAIRS * 20)      // 4800 floats = 19200 B
#define FOLD_F 128                           // fold scratch start (float idx)
#define STAGE0_F 1344                        // stages start (128B-aligned)
#define SMEM_FLOATS (STAGE0_F + NSTAGE * STAGE_FLOATS)
#define SMEM_BYTES (SMEM_FLOATS * 4)         // 82176 B -> 2 CTAs/SM

// ---------------------------------------------------------------------------
// PTX helpers (cp.async.bulk 1D + mbarrier).
// ---------------------------------------------------------------------------
__device__ __forceinline__ unsigned smem_u32(const void* p) {
    unsigned r;
    asm("{ .reg .u64 t; cvta.to.shared.u64 t, %1; cvt.u32.u64 %0, t; }"
        : "=r"(r) : "l"(p));
    return r;
}
__device__ __forceinline__ void mbar_init(unsigned addr, unsigned count) {
    asm volatile("mbarrier.init.shared.b64 [%0], %1;" :: "r"(addr), "r"(count) : "memory");
}
__device__ __forceinline__ void mbar_expect_tx(unsigned addr, unsigned bytes) {
    asm volatile("mbarrier.arrive.expect_tx.shared.b64 _, [%0], %1;"
                 :: "r"(addr), "r"(bytes) : "memory");
}
__device__ __forceinline__ void bulk_load(unsigned dst_smem, const void* src_gmem,
                                          unsigned bytes, unsigned mbar) {
    asm volatile("cp.async.bulk.shared::cta.global.mbarrier::complete_tx::bytes "
                 "[%0], [%1], %2, [%3];"
                 :: "r"(dst_smem), "l"(src_gmem), "r"(bytes), "r"(mbar) : "memory");
}
__device__ __forceinline__ void mbar_wait(unsigned addr, unsigned parity) {
    unsigned done;
    asm volatile("{\n\t.reg .pred p;\n\t"
                 "mbarrier.try_wait.parity.acquire.cta.shared::cta.b64 p, [%1], %2;\n\t"
                 "selp.b32 %0, 1, 0, p;\n\t}"
                 : "=r"(done) : "r"(addr), "r"(parity) : "memory");
    while (!done) {
        asm volatile("{\n\t.reg .pred p;\n\t"
                     "mbarrier.try_wait.parity.acquire.cta.shared::cta.b64 p, [%1], %2, 0x989680;\n\t"
                     "selp.b32 %0, 1, 0, p;\n\t}"
                     : "=r"(done) : "r"(addr), "r"(parity) : "memory");
    }
}

// ---------------------------------------------------------------------------
// Block-wide fold of 10 consecutive affine maps. Combine rule (apply (M,c)
// then layer (Wn,bn)):  M' = Wn@M, c' = Wn@c + bn.  SH_fold = 1210 floats.
// ---------------------------------------------------------------------------
__device__ void fold10(const float* __restrict__ Min, const float* __restrict__ cin,
                       float* __restrict__ Mout, float* __restrict__ cout,
                       float* SH_fold) {
    float* In  = SH_fold;          // 10 x 100
    float* cIn = SH_fold + 1000;   // 10 x 10
    float* M   = SH_fold + 1100;   // 100
    float* cv  = SH_fold + 1200;   // 10
    const int tid = threadIdx.x;

    for (int idx = tid; idx < 1000; idx += TPB) In[idx]  = Min[idx];
    for (int idx = tid; idx < 100;  idx += TPB) cIn[idx] = cin[idx];
    __syncthreads();

    if (tid < 100) M[tid]  = In[tid];
    if (tid < 10)  cv[tid] = cIn[tid];
    __syncthreads();

    const int i = tid / 10;
    const int j = tid % 10;

    #pragma unroll 1
    for (int l = 1; l < 10; ++l) {
        float nm = 0.f, nc = 0.f;
        const float* Wn = &In[l * 100];
        if (tid < 100) {
            #pragma unroll
            for (int k = 0; k < 10; ++k) nm += Wn[i * 10 + k] * M[k * 10 + j];
        }
        if (tid < 10) {
            nc = cIn[l * 10 + tid];
            #pragma unroll
            for (int k = 0; k < 10; ++k) nc += Wn[tid * 10 + k] * cv[k];
        }
        __syncthreads();
        if (tid < 100) M[tid]  = nm;
        if (tid < 10)  cv[tid] = nc;
        __syncthreads();
    }

    if (tid < 100) Mout[tid] = M[tid];
    if (tid < 10)  cout[tid] = cv[tid];
}

// ---------------------------------------------------------------------------
// ONE fused persistent kernel (grid = 296 = 2 CTAs/SM, all resident):
//  1. Every CTA issues its TMA bulk-load prologue immediately (x streaming
//     starts at t=0, independent of the fold).
//  2. CTAs 0..99 fold 10 layers each; CTAs 100..109 fold 10 partials each;
//     CTA 110 folds the last 10 -> g_M3/g_c3, sets g_flag. Others spin.
//  3. All CTAs run the TMA-pipelined apply (proven R6 loop, LDS.64 reads).
// ---------------------------------------------------------------------------
__global__ void __launch_bounds__(TPB, 2) fused_kernel(const float* __restrict__ Ws,
                                                       const float* __restrict__ bs,
                                                       const float* __restrict__ x,
                                                       float* __restrict__ out,
                                                       long long pairs,
                                                       long long rows) {
    extern __shared__ float SH[];
    const int tid = threadIdx.x;
    const int cta = blockIdx.x;

    // mbarriers in the first 64B of smem.
    unsigned bar[NSTAGE];
    #pragma unroll
    for (int s = 0; s < NSTAGE; ++s) bar[s] = smem_u32(&SH[s * 2]);

    if (tid == 0) {
        #pragma unroll
        for (int s = 0; s < NSTAGE; ++s) mbar_init(bar[s], 1);
    }
    __syncthreads();

    const long long tiles   = (pairs + STAGE_PAIRS - 1) / STAGE_PAIRS;
    const long long gstride = gridDim.x;

    // ---- TMA prologue FIRST: fill all stages while the fold runs ----
    if (tid == 0) {
        #pragma unroll
        for (int s = 0; s < NSTAGE; ++s) {
            const long long t = cta + (long long)s * gstride;
            if (t < tiles) {
                const long long pbase = t * STAGE_PAIRS;
                const unsigned np = (unsigned)((pairs - pbase < STAGE_PAIRS)
                                                 ? (pairs - pbase) : STAGE_PAIRS);
                mbar_expect_tx(bar[s], np * 80u);
                bulk_load(smem_u32(&SH[STAGE0_F + s * STAGE_FLOATS]),
                          x + pbase * 20, np * 80u, bar[s]);
            }
        }
    }

    // ---- Fold tree (overlapped with TMA streaming) ----
    float* SHF = SH + FOLD_F;
    if (cta < 100) {
        fold10(Ws + (size_t)cta * 1000, bs + (size_t)cta * 100,
               g_M1 + cta * 100, g_c1 + cta * 10, SHF);
        __threadfence();
        __syncthreads();
        if (tid == 0) atomicAdd(&g_ctr1, 1u);
    } else if (cta < 110) {
        const int d = cta - 100;
        if (tid == 0) {
            while (*(volatile unsigned*)&g_ctr1 < 100u) __nanosleep(64);
        }
        __syncthreads();
        __threadfence();
        fold10(g_M1 + d * 1000, g_c1 + d * 100,
               g_M2 + d * 100, g_c2 + d * 10, SHF);
        __threadfence();
        __syncthreads();
        if (tid == 0) atomicAdd(&g_ctr2, 1u);
    } else if (cta == 110) {
        if (tid == 0) {
            while (*(volatile unsigned*)&g_ctr2 < 10u) __nanosleep(64);
        }
        __syncthreads();
        __threadfence();
        fold10(g_M2, g_c2, g_M3, g_c3, SHF);
        __threadfence();
        __syncthreads();
        if (tid == 0) *(volatile unsigned*)&g_flag = 1u;
    }

    // ---- Wait for the composed affine ----
    if (tid == 0) {
        while (*(volatile unsigned*)&g_flag == 0u) __nanosleep(64);
    }
    __syncthreads();
    __threadfence();   // acquire

    // Per-lane constants. phase = lane%5 decides which 4 output floats.
    const int lane  = tid & 31;
    const int warp  = tid >> 5;
    const int phase = lane % 5;
    const int lp    = lane / 5;              // 5-lane group (0..5; 6 -> inactive)
    const bool active = (lane < 30);
    const int offA = (phase >= 3) ? 10 : 0;  // source row for outputs w=0,1
    const int offB = (phase >= 2) ? 10 : 0;  // source row for outputs w=2,3

    float mw[40], cw[4];
    #pragma unroll
    for (int w = 0; w < 4; ++w) {
        const int jw = (4 * phase + w) % 10;
        cw[w] = __ldg(&g_c3[jw]);
        #pragma unroll
        for (int k = 0; k < 10; ++k) mw[w * 10 + k] = __ldg(&g_M3[jw * 10 + k]);
    }

    float4* out4 = (float4*)out;

    // ---- Main pipelined apply loop ----
    long long i = 0;
    #pragma unroll 1
    for (long long t = cta; t < tiles; t += gstride, ++i) {
        const int s = (int)(i % NSTAGE);
        const unsigned parity = (unsigned)((i / NSTAGE) & 1);
        mbar_wait(bar[s], parity);

        const float* st = &SH[STAGE0_F + s * STAGE_FLOATS];
        const long long tb = t * STAGE_PAIRS;

        #pragma unroll
        for (int it = 0; it < 5; ++it) {
            const int p = warp * 30 + it * 6 + lp;
            const long long gp = tb + p;
            if (active && gp < pairs) {
                const float2* rA = (const float2*)(st + p * 20 + offA);
                const float2* rB = (const float2*)(st + p * 20 + offB);
                float o0 = cw[0], o1 = cw[1], o2 = cw[2], o3 = cw[3];
                #pragma unroll
                for (int kk = 0; kk < 5; ++kk) {
                    const float2 a = rA[kk];
                    const float2 b = rB[kk];
                    o0 = fmaf(mw[2 * kk],          a.x, o0);
                    o0 = fmaf(mw[2 * kk + 1],      a.y, o0);
                    o1 = fmaf(mw[10 + 2 * kk],     a.x, o1);
                    o1 = fmaf(mw[10 + 2 * kk + 1], a.y, o1);
                    o2 = fmaf(mw[20 + 2 * kk],     b.x, o2);
                    o2 = fmaf(mw[20 + 2 * kk + 1], b.y, o2);
                    o3 = fmaf(mw[30 + 2 * kk],     b.x, o3);
                    o3 = fmaf(mw[30 + 2 * kk + 1], b.y, o3);
                }
                out4[gp * 5 + phase] = make_float4(o0, o1, o2, o3);
            }
        }

        __syncthreads();   // all warps done reading stage s
        const long long tn = t + (long long)NSTAGE * gstride;
        if (tn < tiles && tid == 0) {
            const long long pbase = tn * STAGE_PAIRS;
            const unsigned np = (unsigned)((pairs - pbase < STAGE_PAIRS)
                                             ? (pairs - pbase) : STAGE_PAIRS);
            mbar_expect_tx(bar[s], np * 80u);
            bulk_load(smem_u32(&SH[STAGE0_F + s * STAGE_FLOATS]),
                      x + pbase * 20, np * 80u, bar[s]);
        }
    }

    // Odd-row tail (rows is even for this problem; kept for safety).
    if ((rows & 1LL) && cta == 0 && tid == 0) {
        const long long r = rows - 1;
        const float* xr = x + r * 10;
        float h[10];
        #pragma unroll
        for (int k = 0; k < 10; ++k) h[k] = xr[k];
        float* orow = out + r * 10;
        #pragma unroll
        for (int j = 0; j < 10; ++j) {
            float a = __ldg(&g_c3[j]);
            #pragma unroll
            for (int k = 0; k < 10; ++k) a += h[k] * __ldg(&g_M3[j * 10 + k]);
            orow[j] = a;
        }
    }

    // ---- Reset (replay-safe; the LAST CTA to finish resets everything) ----
    __syncthreads();
    __threadfence();
    if (tid == 0) {
        const unsigned old = atomicAdd(&g_done, 1u);
        if (old == gridDim.x - 1) {
            g_done = 0;
            g_ctr1 = 0;
            g_ctr2 = 0;
            g_flag = 0;
        }
    }
}

extern "C" void kernel_launch(void* const* d_in, const int* in_sizes, int n_in,
                              void* d_out, int out_size) {
    // Identify inputs by element count: x=BATCH*10, Ws=1000*100, bs=1000*10.
    const float* x  = nullptr;
    const float* Ws = nullptr;
    const float* bs = nullptr;
    long long x_elems = 0;
    for (int i = 0; i < n_in; ++i) {
        if (in_sizes[i] == 1000 * 100) {
            Ws = (const float*)d_in[i];
        } else if (in_sizes[i] == 1000 * 10) {
            bs = (const float*)d_in[i];
        } else {
            x = (const float*)d_in[i];
            x_elems = in_sizes[i];
        }
    }
    const long long rows  = x_elems / 10;
    const long long pairs = rows >> 1;

    static int smem_set = 0;
    if (!smem_set) {
        cudaFuncSetAttribute(fused_kernel,
                             cudaFuncAttributeMaxDynamicSharedMemorySize, SMEM_BYTES);
        smem_set = 1;
    }
    // 296 CTAs = exactly 2/SM (82KB smem each, 128-reg cap) -> whole grid is
    // wave-1, so the fold spin-waits cannot deadlock.
    fused_kernel<<<296, TPB, SMEM_BYTES>>>(Ws, bs, x, (float*)d_out, pairs, rows);
}